// round 9
// baseline (speedup 1.0000x reference)
#include <cuda_runtime.h>
#include <cuda_bf16.h>
#include <cstdint>

// ---------------- problem constants ----------------
#define B_    4
#define N_    1024
#define CIN_  256
#define HW_   256
#define D_    512
#define IN_   2304
#define ROWS_ 4096

// ---------------- device scratch ----------------
__device__ float g_featsT[(size_t)B_ * HW_ * HW_ * CIN_]; // NHWC, 256 MB
__device__ __nv_bfloat16 g_flat_hi[(size_t)ROWS_ * IN_];  // layout: bin*256+c
__device__ __nv_bfloat16 g_flat_lo[(size_t)ROWS_ * IN_];
__device__ __nv_bfloat16 g_w1t_hi[(size_t)D_ * IN_];      // K-permuted to match
__device__ __nv_bfloat16 g_w1t_lo[(size_t)D_ * IN_];
__device__ __nv_bfloat16 g_w2t_hi[(size_t)D_ * D_];
__device__ __nv_bfloat16 g_w2t_lo[(size_t)D_ * D_];
__device__ __nv_bfloat16 g_hid_hi[(size_t)ROWS_ * D_];
__device__ __nv_bfloat16 g_hid_lo[(size_t)ROWS_ * D_];
__device__ float g_lines[(size_t)ROWS_ * D_];
__device__ float g_outt[(size_t)ROWS_ * D_];

// ---------------- helpers ----------------
#define CP_ASYNC16(dst, src) \
    asm volatile("cp.async.cg.shared.global [%0], [%1], 16;" :: "r"(dst), "l"(src))
#define CP_COMMIT() asm volatile("cp.async.commit_group;" ::: "memory")
#define CP_WAIT(n)  asm volatile("cp.async.wait_group %0;" :: "n"(n) : "memory")

__device__ __forceinline__ void mma16816(float* c, const uint32_t* a, const uint32_t* b) {
    asm volatile(
        "mma.sync.aligned.m16n8k16.row.col.f32.bf16.bf16.f32 "
        "{%0,%1,%2,%3}, {%4,%5,%6,%7}, {%8,%9}, {%0,%1,%2,%3};"
        : "+f"(c[0]), "+f"(c[1]), "+f"(c[2]), "+f"(c[3])
        : "r"(a[0]), "r"(a[1]), "r"(a[2]), "r"(a[3]), "r"(b[0]), "r"(b[1]));
}

__device__ __forceinline__ uint32_t pack_bf16(float x, float y) {
    __nv_bfloat16 hx = __float2bfloat16(x);
    __nv_bfloat16 hy = __float2bfloat16(y);
    return (uint32_t)__bfloat16_as_ushort(hx) | ((uint32_t)__bfloat16_as_ushort(hy) << 16);
}

__device__ __forceinline__ float4 bbox_of(const float* __restrict__ boxes, int n) {
    float4 p0 = *(const float4*)(boxes + (size_t)n * 8);
    float4 p1 = *(const float4*)(boxes + (size_t)n * 8 + 4);
    float4 r;
    r.x = fminf(fminf(p0.x, p0.z), fminf(p1.x, p1.z));
    r.y = fminf(fminf(p0.y, p0.w), fminf(p1.y, p1.w));
    r.z = fmaxf(fmaxf(p0.x, p0.z), fmaxf(p1.x, p1.z));
    r.w = fmaxf(fmaxf(p0.y, p0.w), fmaxf(p1.y, p1.w));
    return r;
}

// ---------------- kernel 1: NCHW -> NHWC transpose -----------------------
__global__ __launch_bounds__(256) void feat_transpose_kernel(const float* __restrict__ in) {
    __shared__ float t[32][129];
    int b  = blockIdx.z;
    int p0 = blockIdx.x * 128;
    int c0 = blockIdx.y * 32;
    const float* ib = in + (size_t)b * CIN_ * (HW_ * HW_);
    float* ob = g_featsT + (size_t)b * (HW_ * HW_) * CIN_;
    const int tid = threadIdx.x;
    {
        int cy   = tid >> 5;
        int col4 = (tid & 31) * 4;
#pragma unroll
        for (int i = 0; i < 4; i++) {
            int c = cy + i * 8;
            float4 v = *(const float4*)(ib + (size_t)(c0 + c) * (HW_ * HW_) + p0 + col4);
            t[c][col4 + 0] = v.x; t[c][col4 + 1] = v.y;
            t[c][col4 + 2] = v.z; t[c][col4 + 3] = v.w;
        }
    }
    __syncthreads();
    {
        int cq = (tid & 7) * 4;
        int pb = tid >> 3;
#pragma unroll
        for (int i = 0; i < 4; i++) {
            int p = pb + i * 32;
            float4 v = make_float4(t[cq + 0][p], t[cq + 1][p], t[cq + 2][p], t[cq + 3][p]);
            *(float4*)(ob + (size_t)(p0 + p) * CIN_ + c0 + cq) = v;
        }
    }
}

// ---------------- kernel 2: both weights, transpose + split (+perm W1) ---
__global__ void wsplit_kernel(const float* __restrict__ W1,
                              const float* __restrict__ W2) {
    __shared__ float tile[32][33];
    const int z  = blockIdx.z;
    const int K  = z ? D_ : IN_;
    if (blockIdx.x * 32 >= K) return;
    const float* W = z ? W2 : W1;
    __nv_bfloat16* Thi = z ? g_w2t_hi : g_w1t_hi;
    __nv_bfloat16* Tlo = z ? g_w2t_lo : g_w1t_lo;

    int j0 = blockIdx.x * 32, n0 = blockIdx.y * 32;
    int tx = threadIdx.x, ty = threadIdx.y;
#pragma unroll
    for (int i = 0; i < 4; i++) {
        int j = j0 + ty + i * 8;
        int k = z ? j : ((j & 255) * 9 + (j >> 8));   // inverse perm
        tile[ty + i * 8][tx] = W[(size_t)k * D_ + n0 + tx];
    }
    __syncthreads();
#pragma unroll
    for (int i = 0; i < 4; i++) {
        float v = tile[tx][ty + i * 8];
        __nv_bfloat16 hi = __float2bfloat16(v);
        size_t idx = (size_t)(n0 + ty + i * 8) * K + j0 + tx;
        Thi[idx] = hi;
        Tlo[idx] = __float2bfloat16(v - __bfloat162float(hi));
    }
}

// ---------------- kernel 3: ROI align, direct coalesced writes -----------
__global__ __launch_bounds__(256, 2) void roi_kernel(const float* __restrict__ boxes) {
    const int tid = threadIdx.x;
    const int grp = tid >> 6;
    const int n   = blockIdx.x * 4 + grp;
    const int b   = n >> 10;
    const int c4  = (tid & 63) * 4;
    const float* fb = g_featsT + (size_t)b * (HW_ * HW_) * CIN_;

    float4 bb = bbox_of(boxes, n);
    float x1 = bb.x * 0.25f, y1 = bb.y * 0.25f;
    float x2 = bb.z * 0.25f, y2 = bb.w * 0.25f;
    float binw = fmaxf(x2 - x1, 1.0f) * (1.0f / 3.0f);
    float binh = fmaxf(y2 - y1, 1.0f) * (1.0f / 3.0f);

    int   yi0[6], yi1[6], xi0[6], xi1[6];
    float yl[6], yv[6], xl[6], xv[6];
#pragma unroll
    for (int s = 0; s < 6; s++) {
        float g = 0.5f * (float)s + 0.25f;
        float yy = y1 + g * binh;
        yv[s] = (yy > -1.0f && yy < 256.0f) ? 1.0f : 0.0f;
        float yc = fminf(fmaxf(yy, 0.0f), 255.0f);
        int i0 = (int)floorf(yc);
        yi0[s] = i0; yi1[s] = min(i0 + 1, 255); yl[s] = yc - (float)i0;

        float xx = x1 + g * binw;
        xv[s] = (xx > -1.0f && xx < 256.0f) ? 1.0f : 0.0f;
        float xc = fminf(fmaxf(xx, 0.0f), 255.0f);
        int j0 = (int)floorf(xc);
        xi0[s] = j0; xi1[s] = min(j0 + 1, 255); xl[s] = xc - (float)j0;
    }

    float4 acc[9];
#pragma unroll
    for (int i = 0; i < 9; i++) acc[i] = make_float4(0.f, 0.f, 0.f, 0.f);

#pragma unroll
    for (int sy = 0; sy < 6; sy++) {
        float ly = yl[sy], hy = 1.0f - ly;
        int r0 = yi0[sy] * 256, r1 = yi1[sy] * 256;
#pragma unroll
        for (int sx = 0; sx < 6; sx++) {
            float lx = xl[sx], hx = 1.0f - lx;
            float w = 0.25f * yv[sy] * xv[sx];
            float w00 = w * hy * hx, w01 = w * hy * lx;
            float w10 = w * ly * hx, w11 = w * ly * lx;
            float4 v00 = *(const float4*)(fb + ((size_t)(r0 + xi0[sx])) * CIN_ + c4);
            float4 v01 = *(const float4*)(fb + ((size_t)(r0 + xi1[sx])) * CIN_ + c4);
            float4 v10 = *(const float4*)(fb + ((size_t)(r1 + xi0[sx])) * CIN_ + c4);
            float4 v11 = *(const float4*)(fb + ((size_t)(r1 + xi1[sx])) * CIN_ + c4);
            int bin = (sy >> 1) * 3 + (sx >> 1);
            acc[bin].x += v00.x * w00 + v01.x * w01 + v10.x * w10 + v11.x * w11;
            acc[bin].y += v00.y * w00 + v01.y * w01 + v10.y * w10 + v11.y * w11;
            acc[bin].z += v00.z * w00 + v01.z * w01 + v10.z * w10 + v11.z * w11;
            acc[bin].w += v00.w * w00 + v01.w * w01 + v10.w * w10 + v11.w * w11;
        }
    }

    size_t base = (size_t)n * IN_;
#pragma unroll
    for (int i = 0; i < 9; i++) {
        float vx = acc[i].x, vy = acc[i].y, vz = acc[i].z, vw = acc[i].w;
        __nv_bfloat16 hx = __float2bfloat16(vx), hy = __float2bfloat16(vy);
        __nv_bfloat16 hz = __float2bfloat16(vz), hw = __float2bfloat16(vw);
        uint32_t hi0 = (uint32_t)__bfloat16_as_ushort(hx) |
                       ((uint32_t)__bfloat16_as_ushort(hy) << 16);
        uint32_t hi1 = (uint32_t)__bfloat16_as_ushort(hz) |
                       ((uint32_t)__bfloat16_as_ushort(hw) << 16);
        uint32_t lo0 = pack_bf16(vx - __bfloat162float(hx), vy - __bfloat162float(hy));
        uint32_t lo1 = pack_bf16(vz - __bfloat162float(hz), vw - __bfloat162float(hw));
        *(uint2*)(g_flat_hi + base + i * 256 + c4) = make_uint2(hi0, hi1);
        *(uint2*)(g_flat_lo + base + i * 256 + c4) = make_uint2(lo0, lo1);
    }
}

// ---------------- GEMM: mma.sync bf16 hi/lo, 64x128x32, term-major -------
// 8 warps (2x4), warp tile 32m x 32n; 2 CTAs/SM.
#define SROW 40
#define A_T  (64 * SROW * 2)             // 5120 B
#define B_T  (128 * SROW * 2)            // 10240 B
#define STAGE (2 * A_T + 2 * B_T)        // 30720 B  [Ahi|Alo|Bhi|Blo]

template <int MODE>
__global__ __launch_bounds__(256, 2) void mma_gemm_kernel(const float* __restrict__ bias) {
    constexpr int K  = (MODE == 0) ? IN_ : D_;
    constexpr int KT = K / 32;

    const __nv_bfloat16* Ahi = (MODE == 0) ? g_flat_hi : g_hid_hi;
    const __nv_bfloat16* Alo = (MODE == 0) ? g_flat_lo : g_hid_lo;
    const __nv_bfloat16* Bhi = (MODE == 0) ? g_w1t_hi : g_w2t_hi;
    const __nv_bfloat16* Blo = (MODE == 0) ? g_w1t_lo : g_w2t_lo;

    extern __shared__ __align__(16) char smem[];   // 2 * STAGE = 61440
    const uint32_t sbase = (uint32_t)__cvta_generic_to_shared(smem);

    const int tid  = threadIdx.x;
    const int wid  = tid >> 5, lane = tid & 31;
    const int g    = lane >> 2, tg = lane & 3;
    const int wm   = wid >> 2, wn = wid & 3;       // 2 x 4 warps; warp = 32m x 32n
    const int bm   = blockIdx.y * 64;
    const int bn   = blockIdx.x * 128;

    float acc[2][4][4];
#pragma unroll
    for (int i = 0; i < 2; i++)
#pragma unroll
        for (int j = 0; j < 4; j++)
#pragma unroll
            for (int q = 0; q < 4; q++) acc[i][j][q] = 0.0f;

    const int ar = tid >> 2, ac = tid & 3;
    auto load_tile = [&](int kt, int s) {
        int kk = kt * 32;
        uint32_t sb = sbase + s * STAGE;
        CP_ASYNC16(sb + ar * (SROW * 2) + ac * 16,
                   (const char*)(Ahi + (size_t)(bm + ar) * K + kk) + ac * 16);
        CP_ASYNC16(sb + A_T + ar * (SROW * 2) + ac * 16,
                   (const char*)(Alo + (size_t)(bm + ar) * K + kk) + ac * 16);
#pragma unroll
        for (int i = 0; i < 2; i++) {
            int id = tid + i * 256;
            int br = id >> 2, bc = id & 3;
            CP_ASYNC16(sb + 2 * A_T + br * (SROW * 2) + bc * 16,
                       (const char*)(Bhi + (size_t)(bn + br) * K + kk) + bc * 16);
            CP_ASYNC16(sb + 2 * A_T + B_T + br * (SROW * 2) + bc * 16,
                       (const char*)(Blo + (size_t)(bn + br) * K + kk) + bc * 16);
        }
    };

    load_tile(0, 0);
    CP_COMMIT();

    int buf = 0;
    for (int kt = 0; kt < KT; kt++) {
        if (kt + 1 < KT) { load_tile(kt + 1, buf ^ 1); CP_COMMIT(); }
        if (kt + 1 < KT) { CP_WAIT(1); } else { CP_WAIT(0); }
        __syncthreads();

        const char* stg = smem + buf * STAGE;
        const __nv_bfloat16* Ah = (const __nv_bfloat16*)(stg);
        const __nv_bfloat16* Al = (const __nv_bfloat16*)(stg + A_T);
        const __nv_bfloat16* Bh = (const __nv_bfloat16*)(stg + 2 * A_T);
        const __nv_bfloat16* Bl = (const __nv_bfloat16*)(stg + 2 * A_T + B_T);

#pragma unroll
        for (int k16 = 0; k16 < 32; k16 += 16) {
            uint32_t ah[2][4], al[2][4], bh[4][2], bl[4][2];
#pragma unroll
            for (int mt = 0; mt < 2; mt++) {
                const __nv_bfloat16* p = Ah + (size_t)(wm * 32 + mt * 16 + g) * SROW + k16 + tg * 2;
                const __nv_bfloat16* q = Al + (size_t)(wm * 32 + mt * 16 + g) * SROW + k16 + tg * 2;
                ah[mt][0] = *(const uint32_t*)(p);
                ah[mt][1] = *(const uint32_t*)(p + 8 * SROW);
                ah[mt][2] = *(const uint32_t*)(p + 8);
                ah[mt][3] = *(const uint32_t*)(p + 8 * SROW + 8);
                al[mt][0] = *(const uint32_t*)(q);
                al[mt][1] = *(const uint32_t*)(q + 8 * SROW);
                al[mt][2] = *(const uint32_t*)(q + 8);
                al[mt][3] = *(const uint32_t*)(q + 8 * SROW + 8);
            }
#pragma unroll
            for (int nt = 0; nt < 4; nt++) {
                const __nv_bfloat16* p = Bh + (size_t)(wn * 32 + nt * 8 + g) * SROW + k16 + tg * 2;
                const __nv_bfloat16* q = Bl + (size_t)(wn * 32 + nt * 8 + g) * SROW + k16 + tg * 2;
                bh[nt][0] = *(const uint32_t*)(p);
                bh[nt][1] = *(const uint32_t*)(p + 8);
                bl[nt][0] = *(const uint32_t*)(q);
                bl[nt][1] = *(const uint32_t*)(q + 8);
            }
            // term-major: dependency distance on each acc = 8 MMAs
#pragma unroll
            for (int mt = 0; mt < 2; mt++)
#pragma unroll
                for (int nt = 0; nt < 4; nt++)
                    mma16816(acc[mt][nt], ah[mt], bh[nt]);   // hi*hi
#pragma unroll
            for (int mt = 0; mt < 2; mt++)
#pragma unroll
                for (int nt = 0; nt < 4; nt++)
                    mma16816(acc[mt][nt], ah[mt], bl[nt]);   // hi*lo
#pragma unroll
            for (int mt = 0; mt < 2; mt++)
#pragma unroll
                for (int nt = 0; nt < 4; nt++)
                    mma16816(acc[mt][nt], al[mt], bh[nt]);   // lo*hi
        }
        __syncthreads();
        buf ^= 1;
    }

    // ---------------- epilogue ----------------
#pragma unroll
    for (int mt = 0; mt < 2; mt++) {
        const int row = bm + wm * 32 + mt * 16 + g;
#pragma unroll
        for (int nt = 0; nt < 4; nt++) {
            const int col = bn + wn * 32 + nt * 8 + 2 * tg;
            float bc0 = bias[col], bc1 = bias[col + 1];
            float v0 = acc[mt][nt][0] + bc0;
            float v1 = acc[mt][nt][1] + bc1;
            float v2 = acc[mt][nt][2] + bc0;
            float v3 = acc[mt][nt][3] + bc1;
            if (MODE == 0) {
                v0 = fmaxf(v0, 0.0f); v1 = fmaxf(v1, 0.0f);
                v2 = fmaxf(v2, 0.0f); v3 = fmaxf(v3, 0.0f);
                __nv_bfloat16 h0 = __float2bfloat16(v0), h1 = __float2bfloat16(v1);
                __nv_bfloat16 h2 = __float2bfloat16(v2), h3 = __float2bfloat16(v3);
                uint32_t hi01 = (uint32_t)__bfloat16_as_ushort(h0) |
                                ((uint32_t)__bfloat16_as_ushort(h1) << 16);
                uint32_t hi23 = (uint32_t)__bfloat16_as_ushort(h2) |
                                ((uint32_t)__bfloat16_as_ushort(h3) << 16);
                uint32_t lo01 = pack_bf16(v0 - __bfloat162float(h0), v1 - __bfloat162float(h1));
                uint32_t lo23 = pack_bf16(v2 - __bfloat162float(h2), v3 - __bfloat162float(h3));
                *(uint32_t*)(g_hid_hi + (size_t)row * D_ + col)       = hi01;
                *(uint32_t*)(g_hid_lo + (size_t)row * D_ + col)       = lo01;
                *(uint32_t*)(g_hid_hi + (size_t)(row + 8) * D_ + col) = hi23;
                *(uint32_t*)(g_hid_lo + (size_t)(row + 8) * D_ + col) = lo23;
            } else {
                *(float2*)(g_lines + (size_t)row * D_ + col)       = make_float2(v0, v1);
                *(float2*)(g_lines + (size_t)(row + 8) * D_ + col) = make_float2(v2, v3);
            }
        }
    }
}

// ---------------- posln (+ masks fill) ----------------
__device__ __forceinline__ float2 block_reduce2(float v0, float v1) {
    __shared__ float s0[16], s1[16];
    int lane = threadIdx.x & 31, wid = threadIdx.x >> 5;
    __syncthreads();
#pragma unroll
    for (int o = 16; o > 0; o >>= 1) {
        v0 += __shfl_down_sync(0xffffffffu, v0, o);
        v1 += __shfl_down_sync(0xffffffffu, v1, o);
    }
    if (lane == 0) { s0[wid] = v0; s1[wid] = v1; }
    __syncthreads();
    if (wid == 0) {
        v0 = (lane < 16) ? s0[lane] : 0.0f;
        v1 = (lane < 16) ? s1[lane] : 0.0f;
#pragma unroll
        for (int o = 8; o > 0; o >>= 1) {
            v0 += __shfl_down_sync(0xffffffffu, v0, o);
            v1 += __shfl_down_sync(0xffffffffu, v1, o);
        }
        if (lane == 0) { s0[0] = v0; s1[0] = v1; }
    }
    __syncthreads();
    return make_float2(s0[0], s1[0]);
}

__global__ __launch_bounds__(512) void posln_kernel(
    const float* __restrict__ img_sizes, const float* __restrict__ boxes,
    const float* __restrict__ Wb, const float* __restrict__ bbv,
    const float* __restrict__ g1, const float* __restrict__ be1,
    const float* __restrict__ g2, const float* __restrict__ be2,
    float* __restrict__ masks) {
    int n = blockIdx.x;
    int b = n >> 10;
    int d = threadIdx.x;

    float4 bb = bbox_of(boxes, n);
    float s0 = __ldg(img_sizes + 2 * b), s1 = __ldg(img_sizes + 2 * b + 1);
    float q0 = bb.x / s0, q1 = bb.y / s1, q2 = bb.z / s0, q3 = bb.w / s1;

    float p = bbv[d] + q0 * Wb[d] + q1 * Wb[D_ + d] + q2 * Wb[2 * D_ + d] + q3 * Wb[3 * D_ + d];
    float2 r = block_reduce2(p, p * p);
    float mu  = r.x * (1.0f / D_);
    float var = r.y * (1.0f / D_) - mu * mu;
    float pos = (p - mu) * rsqrtf(var + 1e-5f) * g1[d] + be1[d];

    float sf = g_lines[(size_t)n * D_ + d] + pos;
    r = block_reduce2(sf, sf * sf);
    mu  = r.x * (1.0f / D_);
    var = r.y * (1.0f / D_) - mu * mu;
    float o = (sf - mu) * rsqrtf(var + 1e-5f) * g2[d] + be2[d];
    g_outt[(size_t)n * D_ + d] = o;

    if (d == 0) masks[n] = 1.0f;
}

// ---------------- (B,N,D) -> (B,D,N) ----------------
__global__ void out_transpose_kernel(float* __restrict__ out) {
    __shared__ float tile[32][33];
    int b  = blockIdx.z;
    int n0 = blockIdx.x * 32;
    int d0 = blockIdx.y * 32;
    int tx = threadIdx.x, ty = threadIdx.y;
#pragma unroll
    for (int i = 0; i < 4; i++)
        tile[ty + i * 8][tx] = g_outt[((size_t)(b << 10) + n0 + ty + i * 8) * D_ + d0 + tx];
    __syncthreads();
#pragma unroll
    for (int i = 0; i < 4; i++)
        out[((size_t)b * D_ + d0 + ty + i * 8) * N_ + n0 + tx] = tile[tx][ty + i * 8];
}

// ---------------- launch ----------------
extern "C" void kernel_launch(void* const* d_in, const int* in_sizes, int n_in,
                              void* d_out, int out_size) {
    const float* feats     = (const float*)d_in[0];
    const float* boxes     = (const float*)d_in[1];
    const float* img_sizes = (const float*)d_in[2];
    const float* W1 = (const float*)d_in[3];
    const float* b1 = (const float*)d_in[4];
    const float* W2 = (const float*)d_in[5];
    const float* b2 = (const float*)d_in[6];
    const float* Wb = (const float*)d_in[7];
    const float* bb = (const float*)d_in[8];
    const float* g1 = (const float*)d_in[9];
    const float* be1 = (const float*)d_in[10];
    const float* g2 = (const float*)d_in[11];
    const float* be2 = (const float*)d_in[12];
    float* out = (float*)d_out;

    const int gsmem = 2 * STAGE;   // 61440
    cudaFuncSetAttribute(mma_gemm_kernel<0>, cudaFuncAttributeMaxDynamicSharedMemorySize, gsmem);
    cudaFuncSetAttribute(mma_gemm_kernel<1>, cudaFuncAttributeMaxDynamicSharedMemorySize, gsmem);

    feat_transpose_kernel<<<dim3(512, 8, 4), 256>>>(feats);                        // 1
    wsplit_kernel<<<dim3(IN_ / 32, D_ / 32, 2), dim3(32, 8)>>>(W1, W2);            // 2
    roi_kernel<<<ROWS_ / 4, 256>>>(boxes);                                         // 3
    mma_gemm_kernel<0><<<dim3(D_ / 128, ROWS_ / 64), 256, gsmem>>>(b1);            // 4 <- profiled
    mma_gemm_kernel<1><<<dim3(D_ / 128, ROWS_ / 64), 256, gsmem>>>(b2);            // 5
    posln_kernel<<<ROWS_, 512>>>(img_sizes, boxes, Wb, bb, g1, be1, g2, be2,
                                 out + (size_t)B_ * D_ * N_);                      // 6
    out_transpose_kernel<<<dim3(32, 16, 4), dim3(32, 8)>>>(out);                   // 7
}

// round 10
// speedup vs baseline: 1.0128x; 1.0128x over previous
#include <cuda_runtime.h>
#include <cuda_bf16.h>
#include <cstdint>

// ---------------- problem constants ----------------
#define B_    4
#define N_    1024
#define CIN_  256
#define HW_   256
#define D_    512
#define IN_   2304
#define ROWS_ 4096

// ---------------- device scratch ----------------
__device__ float g_featsT[(size_t)B_ * HW_ * HW_ * CIN_]; // NHWC, 256 MB
__device__ __nv_bfloat16 g_flat_hi[(size_t)ROWS_ * IN_];  // layout: bin*256+c
__device__ __nv_bfloat16 g_flat_lo[(size_t)ROWS_ * IN_];
__device__ __nv_bfloat16 g_w1t_hi[(size_t)D_ * IN_];      // K-permuted to match
__device__ __nv_bfloat16 g_w1t_lo[(size_t)D_ * IN_];
__device__ __nv_bfloat16 g_w2t_hi[(size_t)D_ * D_];
__device__ __nv_bfloat16 g_w2t_lo[(size_t)D_ * D_];
__device__ __nv_bfloat16 g_hid_hi[(size_t)ROWS_ * D_];
__device__ __nv_bfloat16 g_hid_lo[(size_t)ROWS_ * D_];
__device__ float g_lines[(size_t)ROWS_ * D_];
__device__ float g_outt[(size_t)ROWS_ * D_];

// ---------------- helpers ----------------
#define CP_ASYNC16(dst, src) \
    asm volatile("cp.async.cg.shared.global [%0], [%1], 16;" :: "r"(dst), "l"(src))
#define CP_COMMIT() asm volatile("cp.async.commit_group;" ::: "memory")
#define CP_WAIT(n)  asm volatile("cp.async.wait_group %0;" :: "n"(n) : "memory")

__device__ __forceinline__ void mma16816(float* c, const uint32_t* a, const uint32_t* b) {
    asm volatile(
        "mma.sync.aligned.m16n8k16.row.col.f32.bf16.bf16.f32 "
        "{%0,%1,%2,%3}, {%4,%5,%6,%7}, {%8,%9}, {%0,%1,%2,%3};"
        : "+f"(c[0]), "+f"(c[1]), "+f"(c[2]), "+f"(c[3])
        : "r"(a[0]), "r"(a[1]), "r"(a[2]), "r"(a[3]), "r"(b[0]), "r"(b[1]));
}

__device__ __forceinline__ uint32_t pack_bf16(float x, float y) {
    __nv_bfloat16 hx = __float2bfloat16(x);
    __nv_bfloat16 hy = __float2bfloat16(y);
    return (uint32_t)__bfloat16_as_ushort(hx) | ((uint32_t)__bfloat16_as_ushort(hy) << 16);
}

__device__ __forceinline__ float4 bbox_of(const float* __restrict__ boxes, int n) {
    float4 p0 = *(const float4*)(boxes + (size_t)n * 8);
    float4 p1 = *(const float4*)(boxes + (size_t)n * 8 + 4);
    float4 r;
    r.x = fminf(fminf(p0.x, p0.z), fminf(p1.x, p1.z));
    r.y = fminf(fminf(p0.y, p0.w), fminf(p1.y, p1.w));
    r.z = fmaxf(fmaxf(p0.x, p0.z), fmaxf(p1.x, p1.z));
    r.w = fmaxf(fmaxf(p0.y, p0.w), fmaxf(p1.y, p1.w));
    return r;
}

// ---------------- kernel 1: NCHW -> NHWC transpose -----------------------
__global__ __launch_bounds__(256) void feat_transpose_kernel(const float* __restrict__ in) {
    __shared__ float t[32][129];
    int b  = blockIdx.z;
    int p0 = blockIdx.x * 128;
    int c0 = blockIdx.y * 32;
    const float* ib = in + (size_t)b * CIN_ * (HW_ * HW_);
    float* ob = g_featsT + (size_t)b * (HW_ * HW_) * CIN_;
    const int tid = threadIdx.x;
    {
        int cy   = tid >> 5;
        int col4 = (tid & 31) * 4;
#pragma unroll
        for (int i = 0; i < 4; i++) {
            int c = cy + i * 8;
            float4 v = *(const float4*)(ib + (size_t)(c0 + c) * (HW_ * HW_) + p0 + col4);
            t[c][col4 + 0] = v.x; t[c][col4 + 1] = v.y;
            t[c][col4 + 2] = v.z; t[c][col4 + 3] = v.w;
        }
    }
    __syncthreads();
    {
        int cq = (tid & 7) * 4;
        int pb = tid >> 3;
#pragma unroll
        for (int i = 0; i < 4; i++) {
            int p = pb + i * 32;
            float4 v = make_float4(t[cq + 0][p], t[cq + 1][p], t[cq + 2][p], t[cq + 3][p]);
            *(float4*)(ob + (size_t)(p0 + p) * CIN_ + c0 + cq) = v;
        }
    }
}

// ---------------- kernel 2: both weights, transpose + split (+perm W1) ---
__global__ void wsplit_kernel(const float* __restrict__ W1,
                              const float* __restrict__ W2) {
    __shared__ float tile[32][33];
    const int z  = blockIdx.z;
    const int K  = z ? D_ : IN_;
    if (blockIdx.x * 32 >= K) return;
    const float* W = z ? W2 : W1;
    __nv_bfloat16* Thi = z ? g_w2t_hi : g_w1t_hi;
    __nv_bfloat16* Tlo = z ? g_w2t_lo : g_w1t_lo;

    int j0 = blockIdx.x * 32, n0 = blockIdx.y * 32;
    int tx = threadIdx.x, ty = threadIdx.y;
#pragma unroll
    for (int i = 0; i < 4; i++) {
        int j = j0 + ty + i * 8;
        int k = z ? j : ((j & 255) * 9 + (j >> 8));   // inverse perm
        tile[ty + i * 8][tx] = W[(size_t)k * D_ + n0 + tx];
    }
    __syncthreads();
#pragma unroll
    for (int i = 0; i < 4; i++) {
        float v = tile[tx][ty + i * 8];
        __nv_bfloat16 hi = __float2bfloat16(v);
        size_t idx = (size_t)(n0 + ty + i * 8) * K + j0 + tx;
        Thi[idx] = hi;
        Tlo[idx] = __float2bfloat16(v - __bfloat162float(hi));
    }
}

// ---------------- kernel 3: ROI align, direct coalesced writes -----------
__global__ __launch_bounds__(256, 2) void roi_kernel(const float* __restrict__ boxes) {
    const int tid = threadIdx.x;
    const int grp = tid >> 6;
    const int n   = blockIdx.x * 4 + grp;
    const int b   = n >> 10;
    const int c4  = (tid & 63) * 4;
    const float* fb = g_featsT + (size_t)b * (HW_ * HW_) * CIN_;

    float4 bb = bbox_of(boxes, n);
    float x1 = bb.x * 0.25f, y1 = bb.y * 0.25f;
    float x2 = bb.z * 0.25f, y2 = bb.w * 0.25f;
    float binw = fmaxf(x2 - x1, 1.0f) * (1.0f / 3.0f);
    float binh = fmaxf(y2 - y1, 1.0f) * (1.0f / 3.0f);

    int   yi0[6], yi1[6], xi0[6], xi1[6];
    float yl[6], yv[6], xl[6], xv[6];
#pragma unroll
    for (int s = 0; s < 6; s++) {
        float g = 0.5f * (float)s + 0.25f;
        float yy = y1 + g * binh;
        yv[s] = (yy > -1.0f && yy < 256.0f) ? 1.0f : 0.0f;
        float yc = fminf(fmaxf(yy, 0.0f), 255.0f);
        int i0 = (int)floorf(yc);
        yi0[s] = i0; yi1[s] = min(i0 + 1, 255); yl[s] = yc - (float)i0;

        float xx = x1 + g * binw;
        xv[s] = (xx > -1.0f && xx < 256.0f) ? 1.0f : 0.0f;
        float xc = fminf(fmaxf(xx, 0.0f), 255.0f);
        int j0 = (int)floorf(xc);
        xi0[s] = j0; xi1[s] = min(j0 + 1, 255); xl[s] = xc - (float)j0;
    }

    float4 acc[9];
#pragma unroll
    for (int i = 0; i < 9; i++) acc[i] = make_float4(0.f, 0.f, 0.f, 0.f);

#pragma unroll
    for (int sy = 0; sy < 6; sy++) {
        float ly = yl[sy], hy = 1.0f - ly;
        int r0 = yi0[sy] * 256, r1 = yi1[sy] * 256;
#pragma unroll
        for (int sx = 0; sx < 6; sx++) {
            float lx = xl[sx], hx = 1.0f - lx;
            float w = 0.25f * yv[sy] * xv[sx];
            float w00 = w * hy * hx, w01 = w * hy * lx;
            float w10 = w * ly * hx, w11 = w * ly * lx;
            float4 v00 = *(const float4*)(fb + ((size_t)(r0 + xi0[sx])) * CIN_ + c4);
            float4 v01 = *(const float4*)(fb + ((size_t)(r0 + xi1[sx])) * CIN_ + c4);
            float4 v10 = *(const float4*)(fb + ((size_t)(r1 + xi0[sx])) * CIN_ + c4);
            float4 v11 = *(const float4*)(fb + ((size_t)(r1 + xi1[sx])) * CIN_ + c4);
            int bin = (sy >> 1) * 3 + (sx >> 1);
            acc[bin].x += v00.x * w00 + v01.x * w01 + v10.x * w10 + v11.x * w11;
            acc[bin].y += v00.y * w00 + v01.y * w01 + v10.y * w10 + v11.y * w11;
            acc[bin].z += v00.z * w00 + v01.z * w01 + v10.z * w10 + v11.z * w11;
            acc[bin].w += v00.w * w00 + v01.w * w01 + v10.w * w10 + v11.w * w11;
        }
    }

    size_t base = (size_t)n * IN_;
#pragma unroll
    for (int i = 0; i < 9; i++) {
        float vx = acc[i].x, vy = acc[i].y, vz = acc[i].z, vw = acc[i].w;
        __nv_bfloat16 hx = __float2bfloat16(vx), hy = __float2bfloat16(vy);
        __nv_bfloat16 hz = __float2bfloat16(vz), hw = __float2bfloat16(vw);
        uint32_t hi0 = (uint32_t)__bfloat16_as_ushort(hx) |
                       ((uint32_t)__bfloat16_as_ushort(hy) << 16);
        uint32_t hi1 = (uint32_t)__bfloat16_as_ushort(hz) |
                       ((uint32_t)__bfloat16_as_ushort(hw) << 16);
        uint32_t lo0 = pack_bf16(vx - __bfloat162float(hx), vy - __bfloat162float(hy));
        uint32_t lo1 = pack_bf16(vz - __bfloat162float(hz), vw - __bfloat162float(hw));
        *(uint2*)(g_flat_hi + base + i * 256 + c4) = make_uint2(hi0, hi1);
        *(uint2*)(g_flat_lo + base + i * 256 + c4) = make_uint2(lo0, lo1);
    }
}

// ---------------- GEMM: mma.sync bf16 hi/lo, 128x128x32, 16 warps --------
// Warp grid 4x4, warp tile 32m x 32n. Term-major ordering (dep distance 8).
#define SROW 40
#define A_T  (128 * SROW * 2)            // 10240 B
#define B_T  (128 * SROW * 2)            // 10240 B
#define STAGE (2 * A_T + 2 * B_T)        // 40960 B  [Ahi|Alo|Bhi|Blo]

template <int MODE>
__global__ __launch_bounds__(512, 1) void mma_gemm_kernel(const float* __restrict__ bias) {
    constexpr int K  = (MODE == 0) ? IN_ : D_;
    constexpr int KT = K / 32;

    const __nv_bfloat16* Ahi = (MODE == 0) ? g_flat_hi : g_hid_hi;
    const __nv_bfloat16* Alo = (MODE == 0) ? g_flat_lo : g_hid_lo;
    const __nv_bfloat16* Bhi = (MODE == 0) ? g_w1t_hi : g_w2t_hi;
    const __nv_bfloat16* Blo = (MODE == 0) ? g_w1t_lo : g_w2t_lo;

    extern __shared__ __align__(16) char smem[];   // 2 * STAGE = 81920
    const uint32_t sbase = (uint32_t)__cvta_generic_to_shared(smem);

    const int tid  = threadIdx.x;
    const int wid  = tid >> 5, lane = tid & 31;
    const int g    = lane >> 2, tg = lane & 3;
    const int wm   = wid >> 2, wn = wid & 3;       // 4 x 4 warps; warp = 32m x 32n
    const int bm   = blockIdx.y * 128;
    const int bn   = blockIdx.x * 128;

    float acc[2][4][4];
#pragma unroll
    for (int i = 0; i < 2; i++)
#pragma unroll
        for (int j = 0; j < 4; j++)
#pragma unroll
            for (int q = 0; q < 4; q++) acc[i][j][q] = 0.0f;

    const int lr = tid >> 2, lc = tid & 3;   // 128 rows x 4 chunks, 1/thread/array
    auto load_tile = [&](int kt, int s) {
        int kk = kt * 32;
        uint32_t sb = sbase + s * STAGE;
        uint32_t off = lr * (SROW * 2) + lc * 16;
        size_t gof = (size_t)lr * K + kk + lc * 8;   // 8 bf16 = 16 B
        CP_ASYNC16(sb + off,                 (const char*)(Ahi + (size_t)bm * K + gof));
        CP_ASYNC16(sb + A_T + off,           (const char*)(Alo + (size_t)bm * K + gof));
        CP_ASYNC16(sb + 2 * A_T + off,       (const char*)(Bhi + (size_t)bn * K + gof));
        CP_ASYNC16(sb + 2 * A_T + B_T + off, (const char*)(Blo + (size_t)bn * K + gof));
    };

    load_tile(0, 0);
    CP_COMMIT();

    int buf = 0;
    for (int kt = 0; kt < KT; kt++) {
        if (kt + 1 < KT) { load_tile(kt + 1, buf ^ 1); CP_COMMIT(); }
        if (kt + 1 < KT) { CP_WAIT(1); } else { CP_WAIT(0); }
        __syncthreads();

        const char* stg = smem + buf * STAGE;
        const __nv_bfloat16* Ah = (const __nv_bfloat16*)(stg);
        const __nv_bfloat16* Al = (const __nv_bfloat16*)(stg + A_T);
        const __nv_bfloat16* Bh = (const __nv_bfloat16*)(stg + 2 * A_T);
        const __nv_bfloat16* Bl = (const __nv_bfloat16*)(stg + 2 * A_T + B_T);

#pragma unroll
        for (int k16 = 0; k16 < 32; k16 += 16) {
            uint32_t ah[2][4], al[2][4], bh[4][2], bl[4][2];
#pragma unroll
            for (int mt = 0; mt < 2; mt++) {
                const __nv_bfloat16* p = Ah + (size_t)(wm * 32 + mt * 16 + g) * SROW + k16 + tg * 2;
                const __nv_bfloat16* q = Al + (size_t)(wm * 32 + mt * 16 + g) * SROW + k16 + tg * 2;
                ah[mt][0] = *(const uint32_t*)(p);
                ah[mt][1] = *(const uint32_t*)(p + 8 * SROW);
                ah[mt][2] = *(const uint32_t*)(p + 8);
                ah[mt][3] = *(const uint32_t*)(p + 8 * SROW + 8);
                al[mt][0] = *(const uint32_t*)(q);
                al[mt][1] = *(const uint32_t*)(q + 8 * SROW);
                al[mt][2] = *(const uint32_t*)(q + 8);
                al[mt][3] = *(const uint32_t*)(q + 8 * SROW + 8);
            }
#pragma unroll
            for (int nt = 0; nt < 4; nt++) {
                const __nv_bfloat16* p = Bh + (size_t)(wn * 32 + nt * 8 + g) * SROW + k16 + tg * 2;
                const __nv_bfloat16* q = Bl + (size_t)(wn * 32 + nt * 8 + g) * SROW + k16 + tg * 2;
                bh[nt][0] = *(const uint32_t*)(p);
                bh[nt][1] = *(const uint32_t*)(p + 8);
                bl[nt][0] = *(const uint32_t*)(q);
                bl[nt][1] = *(const uint32_t*)(q + 8);
            }
            // term-major: dependency distance per accumulator = 8 MMAs
#pragma unroll
            for (int mt = 0; mt < 2; mt++)
#pragma unroll
                for (int nt = 0; nt < 4; nt++)
                    mma16816(acc[mt][nt], ah[mt], bh[nt]);   // hi*hi
#pragma unroll
            for (int mt = 0; mt < 2; mt++)
#pragma unroll
                for (int nt = 0; nt < 4; nt++)
                    mma16816(acc[mt][nt], ah[mt], bl[nt]);   // hi*lo
#pragma unroll
            for (int mt = 0; mt < 2; mt++)
#pragma unroll
                for (int nt = 0; nt < 4; nt++)
                    mma16816(acc[mt][nt], al[mt], bh[nt]);   // lo*hi
        }
        __syncthreads();
        buf ^= 1;
    }

    // ---------------- epilogue ----------------
#pragma unroll
    for (int mt = 0; mt < 2; mt++) {
        const int row = bm + wm * 32 + mt * 16 + g;
#pragma unroll
        for (int nt = 0; nt < 4; nt++) {
            const int col = bn + wn * 32 + nt * 8 + 2 * tg;
            float bc0 = bias[col], bc1 = bias[col + 1];
            float v0 = acc[mt][nt][0] + bc0;
            float v1 = acc[mt][nt][1] + bc1;
            float v2 = acc[mt][nt][2] + bc0;
            float v3 = acc[mt][nt][3] + bc1;
            if (MODE == 0) {
                v0 = fmaxf(v0, 0.0f); v1 = fmaxf(v1, 0.0f);
                v2 = fmaxf(v2, 0.0f); v3 = fmaxf(v3, 0.0f);
                __nv_bfloat16 h0 = __float2bfloat16(v0), h1 = __float2bfloat16(v1);
                __nv_bfloat16 h2 = __float2bfloat16(v2), h3 = __float2bfloat16(v3);
                uint32_t hi01 = (uint32_t)__bfloat16_as_ushort(h0) |
                                ((uint32_t)__bfloat16_as_ushort(h1) << 16);
                uint32_t hi23 = (uint32_t)__bfloat16_as_ushort(h2) |
                                ((uint32_t)__bfloat16_as_ushort(h3) << 16);
                uint32_t lo01 = pack_bf16(v0 - __bfloat162float(h0), v1 - __bfloat162float(h1));
                uint32_t lo23 = pack_bf16(v2 - __bfloat162float(h2), v3 - __bfloat162float(h3));
                *(uint32_t*)(g_hid_hi + (size_t)row * D_ + col)       = hi01;
                *(uint32_t*)(g_hid_lo + (size_t)row * D_ + col)       = lo01;
                *(uint32_t*)(g_hid_hi + (size_t)(row + 8) * D_ + col) = hi23;
                *(uint32_t*)(g_hid_lo + (size_t)(row + 8) * D_ + col) = lo23;
            } else {
                *(float2*)(g_lines + (size_t)row * D_ + col)       = make_float2(v0, v1);
                *(float2*)(g_lines + (size_t)(row + 8) * D_ + col) = make_float2(v2, v3);
            }
        }
    }
}

// ---------------- posln (+ masks fill) ----------------
__device__ __forceinline__ float2 block_reduce2(float v0, float v1) {
    __shared__ float s0[16], s1[16];
    int lane = threadIdx.x & 31, wid = threadIdx.x >> 5;
    __syncthreads();
#pragma unroll
    for (int o = 16; o > 0; o >>= 1) {
        v0 += __shfl_down_sync(0xffffffffu, v0, o);
        v1 += __shfl_down_sync(0xffffffffu, v1, o);
    }
    if (lane == 0) { s0[wid] = v0; s1[wid] = v1; }
    __syncthreads();
    if (wid == 0) {
        v0 = (lane < 16) ? s0[lane] : 0.0f;
        v1 = (lane < 16) ? s1[lane] : 0.0f;
#pragma unroll
        for (int o = 8; o > 0; o >>= 1) {
            v0 += __shfl_down_sync(0xffffffffu, v0, o);
            v1 += __shfl_down_sync(0xffffffffu, v1, o);
        }
        if (lane == 0) { s0[0] = v0; s1[0] = v1; }
    }
    __syncthreads();
    return make_float2(s0[0], s1[0]);
}

__global__ __launch_bounds__(512) void posln_kernel(
    const float* __restrict__ img_sizes, const float* __restrict__ boxes,
    const float* __restrict__ Wb, const float* __restrict__ bbv,
    const float* __restrict__ g1, const float* __restrict__ be1,
    const float* __restrict__ g2, const float* __restrict__ be2,
    float* __restrict__ masks) {
    int n = blockIdx.x;
    int b = n >> 10;
    int d = threadIdx.x;

    float4 bb = bbox_of(boxes, n);
    float s0 = __ldg(img_sizes + 2 * b), s1 = __ldg(img_sizes + 2 * b + 1);
    float q0 = bb.x / s0, q1 = bb.y / s1, q2 = bb.z / s0, q3 = bb.w / s1;

    float p = bbv[d] + q0 * Wb[d] + q1 * Wb[D_ + d] + q2 * Wb[2 * D_ + d] + q3 * Wb[3 * D_ + d];
    float2 r = block_reduce2(p, p * p);
    float mu  = r.x * (1.0f / D_);
    float var = r.y * (1.0f / D_) - mu * mu;
    float pos = (p - mu) * rsqrtf(var + 1e-5f) * g1[d] + be1[d];

    float sf = g_lines[(size_t)n * D_ + d] + pos;
    r = block_reduce2(sf, sf * sf);
    mu  = r.x * (1.0f / D_);
    var = r.y * (1.0f / D_) - mu * mu;
    float o = (sf - mu) * rsqrtf(var + 1e-5f) * g2[d] + be2[d];
    g_outt[(size_t)n * D_ + d] = o;

    if (d == 0) masks[n] = 1.0f;
}

// ---------------- (B,N,D) -> (B,D,N) ----------------
__global__ void out_transpose_kernel(float* __restrict__ out) {
    __shared__ float tile[32][33];
    int b  = blockIdx.z;
    int n0 = blockIdx.x * 32;
    int d0 = blockIdx.y * 32;
    int tx = threadIdx.x, ty = threadIdx.y;
#pragma unroll
    for (int i = 0; i < 4; i++)
        tile[ty + i * 8][tx] = g_outt[((size_t)(b << 10) + n0 + ty + i * 8) * D_ + d0 + tx];
    __syncthreads();
#pragma unroll
    for (int i = 0; i < 4; i++)
        out[((size_t)b * D_ + d0 + ty + i * 8) * N_ + n0 + tx] = tile[tx][ty + i * 8];
}

// ---------------- launch ----------------
extern "C" void kernel_launch(void* const* d_in, const int* in_sizes, int n_in,
                              void* d_out, int out_size) {
    const float* feats     = (const float*)d_in[0];
    const float* boxes     = (const float*)d_in[1];
    const float* img_sizes = (const float*)d_in[2];
    const float* W1 = (const float*)d_in[3];
    const float* b1 = (const float*)d_in[4];
    const float* W2 = (const float*)d_in[5];
    const float* b2 = (const float*)d_in[6];
    const float* Wb = (const float*)d_in[7];
    const float* bb = (const float*)d_in[8];
    const float* g1 = (const float*)d_in[9];
    const float* be1 = (const float*)d_in[10];
    const float* g2 = (const float*)d_in[11];
    const float* be2 = (const float*)d_in[12];
    float* out = (float*)d_out;

    const int gsmem = 2 * STAGE;   // 81920
    cudaFuncSetAttribute(mma_gemm_kernel<0>, cudaFuncAttributeMaxDynamicSharedMemorySize, gsmem);
    cudaFuncSetAttribute(mma_gemm_kernel<1>, cudaFuncAttributeMaxDynamicSharedMemorySize, gsmem);

    feat_transpose_kernel<<<dim3(512, 8, 4), 256>>>(feats);                        // 1
    wsplit_kernel<<<dim3(IN_ / 32, D_ / 32, 2), dim3(32, 8)>>>(W1, W2);            // 2
    roi_kernel<<<ROWS_ / 4, 256>>>(boxes);                                         // 3
    mma_gemm_kernel<0><<<dim3(D_ / 128, ROWS_ / 128), 512, gsmem>>>(b1);           // 4 <- profiled
    mma_gemm_kernel<1><<<dim3(D_ / 128, ROWS_ / 128), 512, gsmem>>>(b2);           // 5
    posln_kernel<<<ROWS_, 512>>>(img_sizes, boxes, Wb, bb, g1, be1, g2, be2,
                                 out + (size_t)B_ * D_ * N_);                      // 6
    out_transpose_kernel<<<dim3(32, 16, 4), dim3(32, 8)>>>(out);                   // 7
}

// round 11
// speedup vs baseline: 1.2166x; 1.2012x over previous
#include <cuda_runtime.h>
#include <cuda_fp16.h>
#include <cstdint>

// ---------------- problem constants ----------------
#define B_    4
#define N_    1024
#define CIN_  256
#define HW_   256
#define D_    512
#define IN_   2304
#define ROWS_ 4096

// ---------------- device scratch ----------------
__device__ float g_featsT[(size_t)B_ * HW_ * HW_ * CIN_]; // NHWC, 256 MB
__device__ __half g_flat[(size_t)ROWS_ * IN_];            // layout: bin*256+c
__device__ __half g_w1t_hi[(size_t)D_ * IN_];             // K-permuted to match
__device__ __half g_w1t_lo[(size_t)D_ * IN_];
__device__ __half g_w2t_hi[(size_t)D_ * D_];
__device__ __half g_w2t_lo[(size_t)D_ * D_];
__device__ __half g_hid[(size_t)ROWS_ * D_];
__device__ float g_lines[(size_t)ROWS_ * D_];
__device__ float g_outt[(size_t)ROWS_ * D_];

// ---------------- helpers ----------------
#define CP_ASYNC16(dst, src) \
    asm volatile("cp.async.cg.shared.global [%0], [%1], 16;" :: "r"(dst), "l"(src))
#define CP_COMMIT() asm volatile("cp.async.commit_group;" ::: "memory")
#define CP_WAIT(n)  asm volatile("cp.async.wait_group %0;" :: "n"(n) : "memory")

__device__ __forceinline__ void mma16816(float* c, const uint32_t* a, const uint32_t* b) {
    asm volatile(
        "mma.sync.aligned.m16n8k16.row.col.f32.f16.f16.f32 "
        "{%0,%1,%2,%3}, {%4,%5,%6,%7}, {%8,%9}, {%0,%1,%2,%3};"
        : "+f"(c[0]), "+f"(c[1]), "+f"(c[2]), "+f"(c[3])
        : "r"(a[0]), "r"(a[1]), "r"(a[2]), "r"(a[3]), "r"(b[0]), "r"(b[1]));
}

__device__ __forceinline__ uint32_t pack_h2(float x, float y) {
    __half hx = __float2half_rn(x);
    __half hy = __float2half_rn(y);
    return (uint32_t)__half_as_ushort(hx) | ((uint32_t)__half_as_ushort(hy) << 16);
}

__device__ __forceinline__ float4 bbox_of(const float* __restrict__ boxes, int n) {
    float4 p0 = *(const float4*)(boxes + (size_t)n * 8);
    float4 p1 = *(const float4*)(boxes + (size_t)n * 8 + 4);
    float4 r;
    r.x = fminf(fminf(p0.x, p0.z), fminf(p1.x, p1.z));
    r.y = fminf(fminf(p0.y, p0.w), fminf(p1.y, p1.w));
    r.z = fmaxf(fmaxf(p0.x, p0.z), fmaxf(p1.x, p1.z));
    r.w = fmaxf(fmaxf(p0.y, p0.w), fmaxf(p1.y, p1.w));
    return r;
}

// ---------------- kernel 1: NCHW -> NHWC transpose -----------------------
__global__ __launch_bounds__(256) void feat_transpose_kernel(const float* __restrict__ in) {
    __shared__ float t[32][129];
    int b  = blockIdx.z;
    int p0 = blockIdx.x * 128;
    int c0 = blockIdx.y * 32;
    const float* ib = in + (size_t)b * CIN_ * (HW_ * HW_);
    float* ob = g_featsT + (size_t)b * (HW_ * HW_) * CIN_;
    const int tid = threadIdx.x;
    {
        int cy   = tid >> 5;
        int col4 = (tid & 31) * 4;
#pragma unroll
        for (int i = 0; i < 4; i++) {
            int c = cy + i * 8;
            float4 v = *(const float4*)(ib + (size_t)(c0 + c) * (HW_ * HW_) + p0 + col4);
            t[c][col4 + 0] = v.x; t[c][col4 + 1] = v.y;
            t[c][col4 + 2] = v.z; t[c][col4 + 3] = v.w;
        }
    }
    __syncthreads();
    {
        int cq = (tid & 7) * 4;
        int pb = tid >> 3;
#pragma unroll
        for (int i = 0; i < 4; i++) {
            int p = pb + i * 32;
            float4 v = make_float4(t[cq + 0][p], t[cq + 1][p], t[cq + 2][p], t[cq + 3][p]);
            *(float4*)(ob + (size_t)(p0 + p) * CIN_ + c0 + cq) = v;
        }
    }
}

// ---------------- kernel 2: both weights, transpose + fp16 hi/lo split ---
__global__ void wsplit_kernel(const float* __restrict__ W1,
                              const float* __restrict__ W2) {
    __shared__ float tile[32][33];
    const int z  = blockIdx.z;
    const int K  = z ? D_ : IN_;
    if (blockIdx.x * 32 >= K) return;
    const float* W = z ? W2 : W1;
    __half* Thi = z ? g_w2t_hi : g_w1t_hi;
    __half* Tlo = z ? g_w2t_lo : g_w1t_lo;

    int j0 = blockIdx.x * 32, n0 = blockIdx.y * 32;
    int tx = threadIdx.x, ty = threadIdx.y;
#pragma unroll
    for (int i = 0; i < 4; i++) {
        int j = j0 + ty + i * 8;
        int k = z ? j : ((j & 255) * 9 + (j >> 8));   // inverse perm
        tile[ty + i * 8][tx] = W[(size_t)k * D_ + n0 + tx];
    }
    __syncthreads();
#pragma unroll
    for (int i = 0; i < 4; i++) {
        float v = tile[tx][ty + i * 8];
        __half hi = __float2half_rn(v);
        size_t idx = (size_t)(n0 + ty + i * 8) * K + j0 + tx;
        Thi[idx] = hi;
        Tlo[idx] = __float2half_rn(v - __half2float(hi));
    }
}

// ---------------- kernel 3: ROI align, direct coalesced fp16 writes ------
__global__ __launch_bounds__(256, 2) void roi_kernel(const float* __restrict__ boxes) {
    const int tid = threadIdx.x;
    const int grp = tid >> 6;
    const int n   = blockIdx.x * 4 + grp;
    const int b   = n >> 10;
    const int c4  = (tid & 63) * 4;
    const float* fb = g_featsT + (size_t)b * (HW_ * HW_) * CIN_;

    float4 bb = bbox_of(boxes, n);
    float x1 = bb.x * 0.25f, y1 = bb.y * 0.25f;
    float x2 = bb.z * 0.25f, y2 = bb.w * 0.25f;
    float binw = fmaxf(x2 - x1, 1.0f) * (1.0f / 3.0f);
    float binh = fmaxf(y2 - y1, 1.0f) * (1.0f / 3.0f);

    int   yi0[6], yi1[6], xi0[6], xi1[6];
    float yl[6], yv[6], xl[6], xv[6];
#pragma unroll
    for (int s = 0; s < 6; s++) {
        float g = 0.5f * (float)s + 0.25f;
        float yy = y1 + g * binh;
        yv[s] = (yy > -1.0f && yy < 256.0f) ? 1.0f : 0.0f;
        float yc = fminf(fmaxf(yy, 0.0f), 255.0f);
        int i0 = (int)floorf(yc);
        yi0[s] = i0; yi1[s] = min(i0 + 1, 255); yl[s] = yc - (float)i0;

        float xx = x1 + g * binw;
        xv[s] = (xx > -1.0f && xx < 256.0f) ? 1.0f : 0.0f;
        float xc = fminf(fmaxf(xx, 0.0f), 255.0f);
        int j0 = (int)floorf(xc);
        xi0[s] = j0; xi1[s] = min(j0 + 1, 255); xl[s] = xc - (float)j0;
    }

    float4 acc[9];
#pragma unroll
    for (int i = 0; i < 9; i++) acc[i] = make_float4(0.f, 0.f, 0.f, 0.f);

#pragma unroll
    for (int sy = 0; sy < 6; sy++) {
        float ly = yl[sy], hy = 1.0f - ly;
        int r0 = yi0[sy] * 256, r1 = yi1[sy] * 256;
#pragma unroll
        for (int sx = 0; sx < 6; sx++) {
            float lx = xl[sx], hx = 1.0f - lx;
            float w = 0.25f * yv[sy] * xv[sx];
            float w00 = w * hy * hx, w01 = w * hy * lx;
            float w10 = w * ly * hx, w11 = w * ly * lx;
            float4 v00 = *(const float4*)(fb + ((size_t)(r0 + xi0[sx])) * CIN_ + c4);
            float4 v01 = *(const float4*)(fb + ((size_t)(r0 + xi1[sx])) * CIN_ + c4);
            float4 v10 = *(const float4*)(fb + ((size_t)(r1 + xi0[sx])) * CIN_ + c4);
            float4 v11 = *(const float4*)(fb + ((size_t)(r1 + xi1[sx])) * CIN_ + c4);
            int bin = (sy >> 1) * 3 + (sx >> 1);
            acc[bin].x += v00.x * w00 + v01.x * w01 + v10.x * w10 + v11.x * w11;
            acc[bin].y += v00.y * w00 + v01.y * w01 + v10.y * w10 + v11.y * w11;
            acc[bin].z += v00.z * w00 + v01.z * w01 + v10.z * w10 + v11.z * w11;
            acc[bin].w += v00.w * w00 + v01.w * w01 + v10.w * w10 + v11.w * w11;
        }
    }

    size_t base = (size_t)n * IN_;
#pragma unroll
    for (int i = 0; i < 9; i++) {
        uint32_t p0 = pack_h2(acc[i].x, acc[i].y);
        uint32_t p1 = pack_h2(acc[i].z, acc[i].w);
        *(uint2*)(g_flat + base + i * 256 + c4) = make_uint2(p0, p1);
    }
}

// ---------------- GEMM: mma.sync fp16, A x (Bhi + Blo), 128x128x32 -------
// 8 warps (2x4), warp tile 64m x 32n (R8 config). 2 terms.
#define SROW 40
#define A_T  (128 * SROW * 2)            // 10240 B
#define B_T  (128 * SROW * 2)            // 10240 B
#define STAGE (A_T + 2 * B_T)            // 30720 B  [A|Bhi|Blo]

template <int MODE>
__global__ __launch_bounds__(256, 1) void mma_gemm_kernel(const float* __restrict__ bias) {
    constexpr int K  = (MODE == 0) ? IN_ : D_;
    constexpr int KT = K / 32;

    const __half* A   = (MODE == 0) ? g_flat : g_hid;
    const __half* Bhi = (MODE == 0) ? g_w1t_hi : g_w2t_hi;
    const __half* Blo = (MODE == 0) ? g_w1t_lo : g_w2t_lo;

    extern __shared__ __align__(16) char smem[];   // 2 * STAGE = 61440
    const uint32_t sbase = (uint32_t)__cvta_generic_to_shared(smem);

    const int tid  = threadIdx.x;
    const int wid  = tid >> 5, lane = tid & 31;
    const int g    = lane >> 2, tg = lane & 3;
    const int wm   = wid >> 2, wn = wid & 3;       // 2 x 4 warps; warp = 64m x 32n
    const int bm   = blockIdx.y * 128;
    const int bn   = blockIdx.x * 128;

    float acc[4][4][4];
#pragma unroll
    for (int i = 0; i < 4; i++)
#pragma unroll
        for (int j = 0; j < 4; j++)
#pragma unroll
            for (int q = 0; q < 4; q++) acc[i][j][q] = 0.0f;

    auto load_tile = [&](int kt, int s) {
        int kk = kt * 32;
        uint32_t sb = sbase + s * STAGE;
#pragma unroll
        for (int i = 0; i < 2; i++) {
            int id = tid + i * 256;
            int r = id >> 2, ch = id & 3;
            uint32_t off = r * (SROW * 2) + ch * 16;
            size_t gof = (size_t)r * K + kk + ch * 8;   // 8 halfs = 16 B
            CP_ASYNC16(sb + off,             (const char*)(A   + (size_t)bm * K + gof));
            CP_ASYNC16(sb + A_T + off,       (const char*)(Bhi + (size_t)bn * K + gof));
            CP_ASYNC16(sb + A_T + B_T + off, (const char*)(Blo + (size_t)bn * K + gof));
        }
    };

    load_tile(0, 0);
    CP_COMMIT();

    int buf = 0;
    for (int kt = 0; kt < KT; kt++) {
        if (kt + 1 < KT) { load_tile(kt + 1, buf ^ 1); CP_COMMIT(); }
        if (kt + 1 < KT) { CP_WAIT(1); } else { CP_WAIT(0); }
        __syncthreads();

        const char* stg = smem + buf * STAGE;
        const __half* Ah = (const __half*)(stg);
        const __half* Bh = (const __half*)(stg + A_T);
        const __half* Bl = (const __half*)(stg + A_T + B_T);

#pragma unroll
        for (int k16 = 0; k16 < 32; k16 += 16) {
            uint32_t bh[4][2], bl[4][2];
#pragma unroll
            for (int nt = 0; nt < 4; nt++) {
                const __half* p = Bh + (size_t)(wn * 32 + nt * 8 + g) * SROW + k16 + tg * 2;
                const __half* q = Bl + (size_t)(wn * 32 + nt * 8 + g) * SROW + k16 + tg * 2;
                bh[nt][0] = *(const uint32_t*)(p);
                bh[nt][1] = *(const uint32_t*)(p + 8);
                bl[nt][0] = *(const uint32_t*)(q);
                bl[nt][1] = *(const uint32_t*)(q + 8);
            }
            uint32_t a[4][4];
#pragma unroll
            for (int mt = 0; mt < 4; mt++) {
                const __half* p = Ah + (size_t)(wm * 64 + mt * 16 + g) * SROW + k16 + tg * 2;
                a[mt][0] = *(const uint32_t*)(p);
                a[mt][1] = *(const uint32_t*)(p + 8 * SROW);
                a[mt][2] = *(const uint32_t*)(p + 8);
                a[mt][3] = *(const uint32_t*)(p + 8 * SROW + 8);
            }
            // term-major: dep distance per accumulator = 16 MMAs
#pragma unroll
            for (int mt = 0; mt < 4; mt++)
#pragma unroll
                for (int nt = 0; nt < 4; nt++)
                    mma16816(acc[mt][nt], a[mt], bh[nt]);   // A * Bhi
#pragma unroll
            for (int mt = 0; mt < 4; mt++)
#pragma unroll
                for (int nt = 0; nt < 4; nt++)
                    mma16816(acc[mt][nt], a[mt], bl[nt]);   // A * Blo
        }
        __syncthreads();
        buf ^= 1;
    }

    // ---------------- epilogue ----------------
#pragma unroll
    for (int mt = 0; mt < 4; mt++) {
        const int row = bm + wm * 64 + mt * 16 + g;
#pragma unroll
        for (int nt = 0; nt < 4; nt++) {
            const int col = bn + wn * 32 + nt * 8 + 2 * tg;
            float bc0 = bias[col], bc1 = bias[col + 1];
            float v0 = acc[mt][nt][0] + bc0;
            float v1 = acc[mt][nt][1] + bc1;
            float v2 = acc[mt][nt][2] + bc0;
            float v3 = acc[mt][nt][3] + bc1;
            if (MODE == 0) {
                v0 = fmaxf(v0, 0.0f); v1 = fmaxf(v1, 0.0f);
                v2 = fmaxf(v2, 0.0f); v3 = fmaxf(v3, 0.0f);
                *(uint32_t*)(g_hid + (size_t)row * D_ + col)       = pack_h2(v0, v1);
                *(uint32_t*)(g_hid + (size_t)(row + 8) * D_ + col) = pack_h2(v2, v3);
            } else {
                *(float2*)(g_lines + (size_t)row * D_ + col)       = make_float2(v0, v1);
                *(float2*)(g_lines + (size_t)(row + 8) * D_ + col) = make_float2(v2, v3);
            }
        }
    }
}

// ---------------- posln (+ masks fill) ----------------
__device__ __forceinline__ float2 block_reduce2(float v0, float v1) {
    __shared__ float s0[16], s1[16];
    int lane = threadIdx.x & 31, wid = threadIdx.x >> 5;
    __syncthreads();
#pragma unroll
    for (int o = 16; o > 0; o >>= 1) {
        v0 += __shfl_down_sync(0xffffffffu, v0, o);
        v1 += __shfl_down_sync(0xffffffffu, v1, o);
    }
    if (lane == 0) { s0[wid] = v0; s1[wid] = v1; }
    __syncthreads();
    if (wid == 0) {
        v0 = (lane < 16) ? s0[lane] : 0.0f;
        v1 = (lane < 16) ? s1[lane] : 0.0f;
#pragma unroll
        for (int o = 8; o > 0; o >>= 1) {
            v0 += __shfl_down_sync(0xffffffffu, v0, o);
            v1 += __shfl_down_sync(0xffffffffu, v1, o);
        }
        if (lane == 0) { s0[0] = v0; s1[0] = v1; }
    }
    __syncthreads();
    return make_float2(s0[0], s1[0]);
}

__global__ __launch_bounds__(512) void posln_kernel(
    const float* __restrict__ img_sizes, const float* __restrict__ boxes,
    const float* __restrict__ Wb, const float* __restrict__ bbv,
    const float* __restrict__ g1, const float* __restrict__ be1,
    const float* __restrict__ g2, const float* __restrict__ be2,
    float* __restrict__ masks) {
    int n = blockIdx.x;
    int b = n >> 10;
    int d = threadIdx.x;

    float4 bb = bbox_of(boxes, n);
    float s0 = __ldg(img_sizes + 2 * b), s1 = __ldg(img_sizes + 2 * b + 1);
    float q0 = bb.x / s0, q1 = bb.y / s1, q2 = bb.z / s0, q3 = bb.w / s1;

    float p = bbv[d] + q0 * Wb[d] + q1 * Wb[D_ + d] + q2 * Wb[2 * D_ + d] + q3 * Wb[3 * D_ + d];
    float2 r = block_reduce2(p, p * p);
    float mu  = r.x * (1.0f / D_);
    float var = r.y * (1.0f / D_) - mu * mu;
    float pos = (p - mu) * rsqrtf(var + 1e-5f) * g1[d] + be1[d];

    float sf = g_lines[(size_t)n * D_ + d] + pos;
    r = block_reduce2(sf, sf * sf);
    mu  = r.x * (1.0f / D_);
    var = r.y * (1.0f / D_) - mu * mu;
    float o = (sf - mu) * rsqrtf(var + 1e-5f) * g2[d] + be2[d];
    g_outt[(size_t)n * D_ + d] = o;

    if (d == 0) masks[n] = 1.0f;
}

// ---------------- (B,N,D) -> (B,D,N) ----------------
__global__ void out_transpose_kernel(float* __restrict__ out) {
    __shared__ float tile[32][33];
    int b  = blockIdx.z;
    int n0 = blockIdx.x * 32;
    int d0 = blockIdx.y * 32;
    int tx = threadIdx.x, ty = threadIdx.y;
#pragma unroll
    for (int i = 0; i < 4; i++)
        tile[ty + i * 8][tx] = g_outt[((size_t)(b << 10) + n0 + ty + i * 8) * D_ + d0 + tx];
    __syncthreads();
#pragma unroll
    for (int i = 0; i < 4; i++)
        out[((size_t)b * D_ + d0 + ty + i * 8) * N_ + n0 + tx] = tile[tx][ty + i * 8];
}

// ---------------- launch ----------------
extern "C" void kernel_launch(void* const* d_in, const int* in_sizes, int n_in,
                              void* d_out, int out_size) {
    const float* feats     = (const float*)d_in[0];
    const float* boxes     = (const float*)d_in[1];
    const float* img_sizes = (const float*)d_in[2];
    const float* W1 = (const float*)d_in[3];
    const float* b1 = (const float*)d_in[4];
    const float* W2 = (const float*)d_in[5];
    const float* b2 = (const float*)d_in[6];
    const float* Wb = (const float*)d_in[7];
    const float* bb = (const float*)d_in[8];
    const float* g1 = (const float*)d_in[9];
    const float* be1 = (const float*)d_in[10];
    const float* g2 = (const float*)d_in[11];
    const float* be2 = (const float*)d_in[12];
    float* out = (float*)d_out;

    const int gsmem = 2 * STAGE;   // 61440
    cudaFuncSetAttribute(mma_gemm_kernel<0>, cudaFuncAttributeMaxDynamicSharedMemorySize, gsmem);
    cudaFuncSetAttribute(mma_gemm_kernel<1>, cudaFuncAttributeMaxDynamicSharedMemorySize, gsmem);

    feat_transpose_kernel<<<dim3(512, 8, 4), 256>>>(feats);                        // 1
    wsplit_kernel<<<dim3(IN_ / 32, D_ / 32, 2), dim3(32, 8)>>>(W1, W2);            // 2
    roi_kernel<<<ROWS_ / 4, 256>>>(boxes);                                         // 3
    mma_gemm_kernel<0><<<dim3(D_ / 128, ROWS_ / 128), 256, gsmem>>>(b1);           // 4 <- profiled
    mma_gemm_kernel<1><<<dim3(D_ / 128, ROWS_ / 128), 256, gsmem>>>(b2);           // 5
    posln_kernel<<<ROWS_, 512>>>(img_sizes, boxes, Wb, bb, g1, be1, g2, be2,
                                 out + (size_t)B_ * D_ * N_);                      // 6
    out_transpose_kernel<<<dim3(32, 16, 4), dim3(32, 8)>>>(out);                   // 7
}

// round 12
// speedup vs baseline: 1.5068x; 1.2385x over previous
#include <cuda_runtime.h>
#include <cuda_fp16.h>
#include <cstdint>

// ---------------- problem constants ----------------
#define B_    4
#define N_    1024
#define CIN_  256
#define HW_   256
#define D_    512
#define IN_   2304
#define ROWS_ 4096

// ---------------- device scratch ----------------
__device__ __half g_featsT[(size_t)B_ * HW_ * HW_ * CIN_]; // NHWC fp16, 128 MB
__device__ __half g_flat[(size_t)ROWS_ * IN_];             // layout: bin*256+c
__device__ __half g_w1t[(size_t)D_ * IN_];                 // K-permuted
__device__ __half g_w2t[(size_t)D_ * D_];
__device__ __half g_hid[(size_t)ROWS_ * D_];
__device__ float g_lines[(size_t)ROWS_ * D_];
__device__ float g_outt[(size_t)ROWS_ * D_];

// ---------------- helpers ----------------
#define CP_ASYNC16(dst, src) \
    asm volatile("cp.async.cg.shared.global [%0], [%1], 16;" :: "r"(dst), "l"(src))
#define CP_COMMIT() asm volatile("cp.async.commit_group;" ::: "memory")
#define CP_WAIT(n)  asm volatile("cp.async.wait_group %0;" :: "n"(n) : "memory")

__device__ __forceinline__ void mma16816(float* c, const uint32_t* a, const uint32_t* b) {
    asm volatile(
        "mma.sync.aligned.m16n8k16.row.col.f32.f16.f16.f32 "
        "{%0,%1,%2,%3}, {%4,%5,%6,%7}, {%8,%9}, {%0,%1,%2,%3};"
        : "+f"(c[0]), "+f"(c[1]), "+f"(c[2]), "+f"(c[3])
        : "r"(a[0]), "r"(a[1]), "r"(a[2]), "r"(a[3]), "r"(b[0]), "r"(b[1]));
}

__device__ __forceinline__ uint32_t pack_h2(float x, float y) {
    __half hx = __float2half_rn(x);
    __half hy = __float2half_rn(y);
    return (uint32_t)__half_as_ushort(hx) | ((uint32_t)__half_as_ushort(hy) << 16);
}

__device__ __forceinline__ float4 bbox_of(const float* __restrict__ boxes, int n) {
    float4 p0 = *(const float4*)(boxes + (size_t)n * 8);
    float4 p1 = *(const float4*)(boxes + (size_t)n * 8 + 4);
    float4 r;
    r.x = fminf(fminf(p0.x, p0.z), fminf(p1.x, p1.z));
    r.y = fminf(fminf(p0.y, p0.w), fminf(p1.y, p1.w));
    r.z = fmaxf(fmaxf(p0.x, p0.z), fmaxf(p1.x, p1.z));
    r.w = fmaxf(fmaxf(p0.y, p0.w), fmaxf(p1.y, p1.w));
    return r;
}

// ---------------- kernel 1: NCHW f32 -> NHWC fp16 transpose --------------
__global__ __launch_bounds__(256) void feat_transpose_kernel(const float* __restrict__ in) {
    __shared__ float t[32][129];
    int b  = blockIdx.z;
    int p0 = blockIdx.x * 128;
    int c0 = blockIdx.y * 32;
    const float* ib = in + (size_t)b * CIN_ * (HW_ * HW_);
    __half* ob = g_featsT + (size_t)b * (HW_ * HW_) * CIN_;
    const int tid = threadIdx.x;
    {
        int cy   = tid >> 5;
        int col4 = (tid & 31) * 4;
#pragma unroll
        for (int i = 0; i < 4; i++) {
            int c = cy + i * 8;
            float4 v = *(const float4*)(ib + (size_t)(c0 + c) * (HW_ * HW_) + p0 + col4);
            t[c][col4 + 0] = v.x; t[c][col4 + 1] = v.y;
            t[c][col4 + 2] = v.z; t[c][col4 + 3] = v.w;
        }
    }
    __syncthreads();
    {
        int cq = (tid & 7) * 4;     // channel base
        int pb = tid >> 3;          // pixel
#pragma unroll
        for (int i = 0; i < 4; i++) {
            int p = pb + i * 32;
            uint32_t h0 = pack_h2(t[cq + 0][p], t[cq + 1][p]);
            uint32_t h1 = pack_h2(t[cq + 2][p], t[cq + 3][p]);
            *(uint2*)(ob + (size_t)(p0 + p) * CIN_ + c0 + cq) = make_uint2(h0, h1);
        }
    }
}

// ---------------- kernel 2: both weights, transpose + fp16 (+perm W1) ----
__global__ void wsplit_kernel(const float* __restrict__ W1,
                              const float* __restrict__ W2) {
    __shared__ float tile[32][33];
    const int z  = blockIdx.z;
    const int K  = z ? D_ : IN_;
    if (blockIdx.x * 32 >= K) return;
    const float* W = z ? W2 : W1;
    __half* T = z ? g_w2t : g_w1t;

    int j0 = blockIdx.x * 32, n0 = blockIdx.y * 32;
    int tx = threadIdx.x, ty = threadIdx.y;
#pragma unroll
    for (int i = 0; i < 4; i++) {
        int j = j0 + ty + i * 8;
        int k = z ? j : ((j & 255) * 9 + (j >> 8));   // inverse perm
        tile[ty + i * 8][tx] = W[(size_t)k * D_ + n0 + tx];
    }
    __syncthreads();
#pragma unroll
    for (int i = 0; i < 4; i++) {
        float v = tile[tx][ty + i * 8];
        T[(size_t)(n0 + ty + i * 8) * K + j0 + tx] = __float2half_rn(v);
    }
}

// ---------------- kernel 3: ROI align on fp16 feats ----------------------
__global__ __launch_bounds__(256, 2) void roi_kernel(const float* __restrict__ boxes) {
    const int tid = threadIdx.x;
    const int grp = tid >> 6;
    const int n   = blockIdx.x * 4 + grp;
    const int b   = n >> 10;
    const int c4  = (tid & 63) * 4;
    const __half* fb = g_featsT + (size_t)b * (HW_ * HW_) * CIN_;

    float4 bb = bbox_of(boxes, n);
    float x1 = bb.x * 0.25f, y1 = bb.y * 0.25f;
    float x2 = bb.z * 0.25f, y2 = bb.w * 0.25f;
    float binw = fmaxf(x2 - x1, 1.0f) * (1.0f / 3.0f);
    float binh = fmaxf(y2 - y1, 1.0f) * (1.0f / 3.0f);

    int   yi0[6], yi1[6], xi0[6], xi1[6];
    float yl[6], yv[6], xl[6], xv[6];
#pragma unroll
    for (int s = 0; s < 6; s++) {
        float g = 0.5f * (float)s + 0.25f;
        float yy = y1 + g * binh;
        yv[s] = (yy > -1.0f && yy < 256.0f) ? 1.0f : 0.0f;
        float yc = fminf(fmaxf(yy, 0.0f), 255.0f);
        int i0 = (int)floorf(yc);
        yi0[s] = i0; yi1[s] = min(i0 + 1, 255); yl[s] = yc - (float)i0;

        float xx = x1 + g * binw;
        xv[s] = (xx > -1.0f && xx < 256.0f) ? 1.0f : 0.0f;
        float xc = fminf(fmaxf(xx, 0.0f), 255.0f);
        int j0 = (int)floorf(xc);
        xi0[s] = j0; xi1[s] = min(j0 + 1, 255); xl[s] = xc - (float)j0;
    }

    float4 acc[9];
#pragma unroll
    for (int i = 0; i < 9; i++) acc[i] = make_float4(0.f, 0.f, 0.f, 0.f);

#pragma unroll
    for (int sy = 0; sy < 6; sy++) {
        float ly = yl[sy], hy = 1.0f - ly;
        int r0 = yi0[sy] * 256, r1 = yi1[sy] * 256;
#pragma unroll
        for (int sx = 0; sx < 6; sx++) {
            float lx = xl[sx], hx = 1.0f - lx;
            float w = 0.25f * yv[sy] * xv[sx];
            float w00 = w * hy * hx, w01 = w * hy * lx;
            float w10 = w * ly * hx, w11 = w * ly * lx;
            const __half2* p00 = (const __half2*)(fb + ((size_t)(r0 + xi0[sx])) * CIN_ + c4);
            const __half2* p01 = (const __half2*)(fb + ((size_t)(r0 + xi1[sx])) * CIN_ + c4);
            const __half2* p10 = (const __half2*)(fb + ((size_t)(r1 + xi0[sx])) * CIN_ + c4);
            const __half2* p11 = (const __half2*)(fb + ((size_t)(r1 + xi1[sx])) * CIN_ + c4);
            float2 a00 = __half22float2(p00[0]), b00 = __half22float2(p00[1]);
            float2 a01 = __half22float2(p01[0]), b01 = __half22float2(p01[1]);
            float2 a10 = __half22float2(p10[0]), b10 = __half22float2(p10[1]);
            float2 a11 = __half22float2(p11[0]), b11 = __half22float2(p11[1]);
            int bin = (sy >> 1) * 3 + (sx >> 1);
            acc[bin].x += a00.x * w00 + a01.x * w01 + a10.x * w10 + a11.x * w11;
            acc[bin].y += a00.y * w00 + a01.y * w01 + a10.y * w10 + a11.y * w11;
            acc[bin].z += b00.x * w00 + b01.x * w01 + b10.x * w10 + b11.x * w11;
            acc[bin].w += b00.y * w00 + b01.y * w01 + b10.y * w10 + b11.y * w11;
        }
    }

    size_t base = (size_t)n * IN_;
#pragma unroll
    for (int i = 0; i < 9; i++) {
        uint32_t p0 = pack_h2(acc[i].x, acc[i].y);
        uint32_t p1 = pack_h2(acc[i].z, acc[i].w);
        *(uint2*)(g_flat + base + i * 256 + c4) = make_uint2(p0, p1);
    }
}

// ---------------- GEMM: mma.sync fp16 single-term, 128x128x32 ------------
// 8 warps (2x4), warp tile 64m x 32n (R8 config).
#define SROW 40
#define A_T  (128 * SROW * 2)            // 10240 B
#define B_T  (128 * SROW * 2)            // 10240 B
#define STAGE (A_T + B_T)                // 20480 B  [A|B]

template <int MODE>
__global__ __launch_bounds__(256, 1) void mma_gemm_kernel(const float* __restrict__ bias) {
    constexpr int K  = (MODE == 0) ? IN_ : D_;
    constexpr int KT = K / 32;

    const __half* A  = (MODE == 0) ? g_flat : g_hid;
    const __half* Bw = (MODE == 0) ? g_w1t : g_w2t;

    extern __shared__ __align__(16) char smem[];   // 2 * STAGE = 40960
    const uint32_t sbase = (uint32_t)__cvta_generic_to_shared(smem);

    const int tid  = threadIdx.x;
    const int wid  = tid >> 5, lane = tid & 31;
    const int g    = lane >> 2, tg = lane & 3;
    const int wm   = wid >> 2, wn = wid & 3;       // 2 x 4 warps; warp = 64m x 32n
    const int bm   = blockIdx.y * 128;
    const int bn   = blockIdx.x * 128;

    float acc[4][4][4];
#pragma unroll
    for (int i = 0; i < 4; i++)
#pragma unroll
        for (int j = 0; j < 4; j++)
#pragma unroll
            for (int q = 0; q < 4; q++) acc[i][j][q] = 0.0f;

    auto load_tile = [&](int kt, int s) {
        int kk = kt * 32;
        uint32_t sb = sbase + s * STAGE;
#pragma unroll
        for (int i = 0; i < 2; i++) {
            int id = tid + i * 256;
            int r = id >> 2, ch = id & 3;
            uint32_t off = r * (SROW * 2) + ch * 16;
            size_t gof = (size_t)r * K + kk + ch * 8;   // 8 halfs = 16 B
            CP_ASYNC16(sb + off,       (const char*)(A  + (size_t)bm * K + gof));
            CP_ASYNC16(sb + A_T + off, (const char*)(Bw + (size_t)bn * K + gof));
        }
    };

    load_tile(0, 0);
    CP_COMMIT();

    int buf = 0;
    for (int kt = 0; kt < KT; kt++) {
        if (kt + 1 < KT) { load_tile(kt + 1, buf ^ 1); CP_COMMIT(); }
        if (kt + 1 < KT) { CP_WAIT(1); } else { CP_WAIT(0); }
        __syncthreads();

        const char* stg = smem + buf * STAGE;
        const __half* Ah = (const __half*)(stg);
        const __half* Bh = (const __half*)(stg + A_T);

#pragma unroll
        for (int k16 = 0; k16 < 32; k16 += 16) {
            uint32_t bfr[4][2];
#pragma unroll
            for (int nt = 0; nt < 4; nt++) {
                const __half* p = Bh + (size_t)(wn * 32 + nt * 8 + g) * SROW + k16 + tg * 2;
                bfr[nt][0] = *(const uint32_t*)(p);
                bfr[nt][1] = *(const uint32_t*)(p + 8);
            }
            uint32_t a[4][4];
#pragma unroll
            for (int mt = 0; mt < 4; mt++) {
                const __half* p = Ah + (size_t)(wm * 64 + mt * 16 + g) * SROW + k16 + tg * 2;
                a[mt][0] = *(const uint32_t*)(p);
                a[mt][1] = *(const uint32_t*)(p + 8 * SROW);
                a[mt][2] = *(const uint32_t*)(p + 8);
                a[mt][3] = *(const uint32_t*)(p + 8 * SROW + 8);
            }
#pragma unroll
            for (int mt = 0; mt < 4; mt++)
#pragma unroll
                for (int nt = 0; nt < 4; nt++)
                    mma16816(acc[mt][nt], a[mt], bfr[nt]);
        }
        __syncthreads();
        buf ^= 1;
    }

    // ---------------- epilogue ----------------
#pragma unroll
    for (int mt = 0; mt < 4; mt++) {
        const int row = bm + wm * 64 + mt * 16 + g;
#pragma unroll
        for (int nt = 0; nt < 4; nt++) {
            const int col = bn + wn * 32 + nt * 8 + 2 * tg;
            float bc0 = bias[col], bc1 = bias[col + 1];
            float v0 = acc[mt][nt][0] + bc0;
            float v1 = acc[mt][nt][1] + bc1;
            float v2 = acc[mt][nt][2] + bc0;
            float v3 = acc[mt][nt][3] + bc1;
            if (MODE == 0) {
                v0 = fmaxf(v0, 0.0f); v1 = fmaxf(v1, 0.0f);
                v2 = fmaxf(v2, 0.0f); v3 = fmaxf(v3, 0.0f);
                *(uint32_t*)(g_hid + (size_t)row * D_ + col)       = pack_h2(v0, v1);
                *(uint32_t*)(g_hid + (size_t)(row + 8) * D_ + col) = pack_h2(v2, v3);
            } else {
                *(float2*)(g_lines + (size_t)row * D_ + col)       = make_float2(v0, v1);
                *(float2*)(g_lines + (size_t)(row + 8) * D_ + col) = make_float2(v2, v3);
            }
        }
    }
}

// ---------------- posln (+ masks fill) ----------------
__device__ __forceinline__ float2 block_reduce2(float v0, float v1) {
    __shared__ float s0[16], s1[16];
    int lane = threadIdx.x & 31, wid = threadIdx.x >> 5;
    __syncthreads();
#pragma unroll
    for (int o = 16; o > 0; o >>= 1) {
        v0 += __shfl_down_sync(0xffffffffu, v0, o);
        v1 += __shfl_down_sync(0xffffffffu, v1, o);
    }
    if (lane == 0) { s0[wid] = v0; s1[wid] = v1; }
    __syncthreads();
    if (wid == 0) {
        v0 = (lane < 16) ? s0[lane] : 0.0f;
        v1 = (lane < 16) ? s1[lane] : 0.0f;
#pragma unroll
        for (int o = 8; o > 0; o >>= 1) {
            v0 += __shfl_down_sync(0xffffffffu, v0, o);
            v1 += __shfl_down_sync(0xffffffffu, v1, o);
        }
        if (lane == 0) { s0[0] = v0; s1[0] = v1; }
    }
    __syncthreads();
    return make_float2(s0[0], s1[0]);
}

__global__ __launch_bounds__(512) void posln_kernel(
    const float* __restrict__ img_sizes, const float* __restrict__ boxes,
    const float* __restrict__ Wb, const float* __restrict__ bbv,
    const float* __restrict__ g1, const float* __restrict__ be1,
    const float* __restrict__ g2, const float* __restrict__ be2,
    float* __restrict__ masks) {
    int n = blockIdx.x;
    int b = n >> 10;
    int d = threadIdx.x;

    float4 bb = bbox_of(boxes, n);
    float s0 = __ldg(img_sizes + 2 * b), s1 = __ldg(img_sizes + 2 * b + 1);
    float q0 = bb.x / s0, q1 = bb.y / s1, q2 = bb.z / s0, q3 = bb.w / s1;

    float p = bbv[d] + q0 * Wb[d] + q1 * Wb[D_ + d] + q2 * Wb[2 * D_ + d] + q3 * Wb[3 * D_ + d];
    float2 r = block_reduce2(p, p * p);
    float mu  = r.x * (1.0f / D_);
    float var = r.y * (1.0f / D_) - mu * mu;
    float pos = (p - mu) * rsqrtf(var + 1e-5f) * g1[d] + be1[d];

    float sf = g_lines[(size_t)n * D_ + d] + pos;
    r = block_reduce2(sf, sf * sf);
    mu  = r.x * (1.0f / D_);
    var = r.y * (1.0f / D_) - mu * mu;
    float o = (sf - mu) * rsqrtf(var + 1e-5f) * g2[d] + be2[d];
    g_outt[(size_t)n * D_ + d] = o;

    if (d == 0) masks[n] = 1.0f;
}

// ---------------- (B,N,D) -> (B,D,N) ----------------
__global__ void out_transpose_kernel(float* __restrict__ out) {
    __shared__ float tile[32][33];
    int b  = blockIdx.z;
    int n0 = blockIdx.x * 32;
    int d0 = blockIdx.y * 32;
    int tx = threadIdx.x, ty = threadIdx.y;
#pragma unroll
    for (int i = 0; i < 4; i++)
        tile[ty + i * 8][tx] = g_outt[((size_t)(b << 10) + n0 + ty + i * 8) * D_ + d0 + tx];
    __syncthreads();
#pragma unroll
    for (int i = 0; i < 4; i++)
        out[((size_t)b * D_ + d0 + ty + i * 8) * N_ + n0 + tx] = tile[tx][ty + i * 8];
}

// ---------------- launch ----------------
extern "C" void kernel_launch(void* const* d_in, const int* in_sizes, int n_in,
                              void* d_out, int out_size) {
    const float* feats     = (const float*)d_in[0];
    const float* boxes     = (const float*)d_in[1];
    const float* img_sizes = (const float*)d_in[2];
    const float* W1 = (const float*)d_in[3];
    const float* b1 = (const float*)d_in[4];
    const float* W2 = (const float*)d_in[5];
    const float* b2 = (const float*)d_in[6];
    const float* Wb = (const float*)d_in[7];
    const float* bb = (const float*)d_in[8];
    const float* g1 = (const float*)d_in[9];
    const float* be1 = (const float*)d_in[10];
    const float* g2 = (const float*)d_in[11];
    const float* be2 = (const float*)d_in[12];
    float* out = (float*)d_out;

    const int gsmem = 2 * STAGE;   // 40960
    cudaFuncSetAttribute(mma_gemm_kernel<0>, cudaFuncAttributeMaxDynamicSharedMemorySize, gsmem);
    cudaFuncSetAttribute(mma_gemm_kernel<1>, cudaFuncAttributeMaxDynamicSharedMemorySize, gsmem);

    feat_transpose_kernel<<<dim3(512, 8, 4), 256>>>(feats);                        // 1
    wsplit_kernel<<<dim3(IN_ / 32, D_ / 32, 2), dim3(32, 8)>>>(W1, W2);            // 2
    roi_kernel<<<ROWS_ / 4, 256>>>(boxes);                                         // 3
    mma_gemm_kernel<0><<<dim3(D_ / 128, ROWS_ / 128), 256, gsmem>>>(b1);           // 4 <- profiled
    mma_gemm_kernel<1><<<dim3(D_ / 128, ROWS_ / 128), 256, gsmem>>>(b2);           // 5
    posln_kernel<<<ROWS_, 512>>>(img_sizes, boxes, Wb, bb, g1, be1, g2, be2,
                                 out + (size_t)B_ * D_ * N_);                      // 6
    out_transpose_kernel<<<dim3(32, 16, 4), dim3(32, 8)>>>(out);                   // 7
}